// round 3
// baseline (speedup 1.0000x reference)
#include <cuda_runtime.h>

#define N_NODE 100000
#define N_EDGE 1600000
#define D_IN   128
#define D_EDGE 16

// Scratch (allocation-free: __device__ globals)
__device__ float g_acc [N_NODE * D_IN];    // x + weighted neighbor sum
__device__ float g_eagg[N_NODE * D_EDGE];  // weighted edge-feature sum
__device__ float g_h0  [N_NODE * D_IN];    // acc + eagg @ W_edge + b_edge
__device__ float g_h1  [N_NODE * D_IN];    // relu(h0 @ W1 + b1)
__device__ int   g_is64;

// ---------------------------------------------------------------------------
// Detect whether edge_list is int64 or int32: int64 values < 2^31 have all
// odd int32 words == 0 (little endian). Random int32 dst values make that
// astronomically unlikely for real int32 data.
__global__ void detect_kernel(const int* el)
{
    int is64 = 1;
    for (int i = 1; i < 4096; i += 2) {
        if (el[i] != 0) { is64 = 0; break; }
    }
    g_is64 = is64;
}

// ---------------------------------------------------------------------------
// acc = x ; eagg = 0
__global__ void init_kernel(const float* __restrict__ x)
{
    int i = blockIdx.x * blockDim.x + threadIdx.x;
    const int n1 = N_NODE * D_IN / 4;
    const int n2 = N_NODE * D_EDGE / 4;
    if (i < n1) ((float4*)g_acc)[i] = ((const float4*)x)[i];
    if (i < n2) ((float4*)g_eagg)[i] = make_float4(0.f, 0.f, 0.f, 0.f);
}

// ---------------------------------------------------------------------------
// One warp per edge:
//   acc[dst][:]  += x[src][:]  * w     (128 floats, 4 per lane, coalesced RED)
//   eagg[dst][:] += ef[e][:]   * w     (16 floats, lanes 0..15)
__global__ __launch_bounds__(256) void scatter_kernel(
    const void* __restrict__ el_raw,
    const float* __restrict__ ew,
    const float* __restrict__ ef,
    const float* __restrict__ x)
{
    int gw   = (blockIdx.x * blockDim.x + threadIdx.x) >> 5;
    int lane = threadIdx.x & 31;
    if (gw >= N_EDGE) return;

    int src, dst;
    if (g_is64) {
        const long long* el = (const long long*)el_raw;
        src = (int)__ldg(&el[2 * gw]);
        dst = (int)__ldg(&el[2 * gw + 1]);
    } else {
        const int* el = (const int*)el_raw;
        src = __ldg(&el[2 * gw]);
        dst = __ldg(&el[2 * gw + 1]);
    }
    float w = __ldg(&ew[gw]);

    const float4* xr = (const float4*)(x + (size_t)src * D_IN);
    float*        ar = g_acc + (size_t)dst * D_IN;

    float4 v = __ldg(&xr[lane]);
    atomicAdd(ar + lane * 4 + 0, v.x * w);
    atomicAdd(ar + lane * 4 + 1, v.y * w);
    atomicAdd(ar + lane * 4 + 2, v.z * w);
    atomicAdd(ar + lane * 4 + 3, v.w * w);

    if (lane < D_EDGE) {
        float e = __ldg(&ef[(size_t)gw * D_EDGE + lane]);
        atomicAdd(&g_eagg[(size_t)dst * D_EDGE + lane], e * w);
    }
}

// ---------------------------------------------------------------------------
// h0 = acc + eagg @ W_edge + b_edge     (one warp per node)
__global__ __launch_bounds__(256) void h0_kernel(
    const float* __restrict__ W_edge,
    const float* __restrict__ b_edge)
{
    __shared__ float we[D_EDGE * D_IN];  // 8 KB
    __shared__ float be[D_IN];
    int tid = threadIdx.x;
    for (int i = tid; i < D_EDGE * D_IN; i += 256) we[i] = W_edge[i];
    if (tid < D_IN) be[tid] = b_edge[tid];
    __syncthreads();

    int node = (blockIdx.x * 256 + tid) >> 5;
    int lane = tid & 31;
    if (node >= N_NODE) return;

    float ev = (lane < D_EDGE) ? g_eagg[(size_t)node * D_EDGE + lane] : 0.f;
    float4 r = ((const float4*)g_acc)[(size_t)node * 32 + lane];
    float4 bb = ((const float4*)be)[lane];
    r.x += bb.x; r.y += bb.y; r.z += bb.z; r.w += bb.w;

#pragma unroll
    for (int i = 0; i < D_EDGE; i++) {
        float e = __shfl_sync(0xffffffffu, ev, i);
        float4 wv = ((const float4*)we)[i * 32 + lane];
        r.x += e * wv.x; r.y += e * wv.y; r.z += e * wv.z; r.w += e * wv.w;
    }
    ((float4*)g_h0)[(size_t)node * 32 + lane] = r;
}

// ---------------------------------------------------------------------------
// out = relu(in @ W + b), 128x128 W resident in smem, ROWS-row input tile.
// Templated on tile rows so we have a 96 KB fallback if 128 KB smem is
// unavailable. Thread (tid): j4 = tid&31 (4 output cols), rb = tid>>5.
template <int TILE_ROWS>
__global__ __launch_bounds__(256, 1) void mlp_kernel_t(
    const float* __restrict__ W,
    const float* __restrict__ b,
    float* __restrict__ ext_out,
    int layer)
{
    extern __shared__ float smem[];
    float* Ws = smem;                  // 128*128 floats (64 KB)
    float* Is = smem + 16384;          // TILE_ROWS*128 floats
    __shared__ float bs[D_IN];

    constexpr int ROWS_PER_THREAD = TILE_ROWS / 8;  // 16 or 8

    const float* in  = (layer == 0) ? g_h0 : g_h1;
    float*       out = (layer == 0) ? g_h1 : ext_out;

    int tid = threadIdx.x;
    for (int i = tid; i < 4096; i += 256)
        ((float4*)Ws)[i] = ((const float4*)W)[i];
    if (tid < D_IN) bs[tid] = b[tid];

    int row0 = blockIdx.x * TILE_ROWS;
    for (int i = tid; i < TILE_ROWS * 32; i += 256) {
        int r = i >> 5, c = i & 31;
        int row = row0 + r;
        ((float4*)Is)[i] = (row < N_NODE)
            ? ((const float4*)in)[(size_t)row * 32 + c]
            : make_float4(0.f, 0.f, 0.f, 0.f);
    }
    __syncthreads();

    int j4 = tid & 31;   // output float4 column
    int rb = tid >> 5;   // row block

    float4 acc[ROWS_PER_THREAD];
#pragma unroll
    for (int r = 0; r < ROWS_PER_THREAD; r++) acc[r] = make_float4(0.f, 0.f, 0.f, 0.f);

    for (int k = 0; k < 128; k += 4) {
        float4 w0 = ((const float4*)Ws)[(k + 0) * 32 + j4];
        float4 w1 = ((const float4*)Ws)[(k + 1) * 32 + j4];
        float4 w2 = ((const float4*)Ws)[(k + 2) * 32 + j4];
        float4 w3 = ((const float4*)Ws)[(k + 3) * 32 + j4];
#pragma unroll
        for (int r = 0; r < ROWS_PER_THREAD; r++) {
            float4 a = ((const float4*)Is)[(rb * ROWS_PER_THREAD + r) * 32 + (k >> 2)];
            acc[r].x += a.x * w0.x + a.y * w1.x + a.z * w2.x + a.w * w3.x;
            acc[r].y += a.x * w0.y + a.y * w1.y + a.z * w2.y + a.w * w3.y;
            acc[r].z += a.x * w0.z + a.y * w1.z + a.z * w2.z + a.w * w3.z;
            acc[r].w += a.x * w0.w + a.y * w1.w + a.z * w2.w + a.w * w3.w;
        }
    }

    float4 bb = ((const float4*)bs)[j4];
#pragma unroll
    for (int r = 0; r < ROWS_PER_THREAD; r++) {
        int row = row0 + rb * ROWS_PER_THREAD + r;
        if (row < N_NODE) {
            float4 v = acc[r];
            v.x = fmaxf(v.x + bb.x, 0.f);
            v.y = fmaxf(v.y + bb.y, 0.f);
            v.z = fmaxf(v.z + bb.z, 0.f);
            v.w = fmaxf(v.w + bb.w, 0.f);
            ((float4*)out)[(size_t)row * 32 + j4] = v;
        }
    }
}

// ---------------------------------------------------------------------------
extern "C" void kernel_launch(void* const* d_in, const int* in_sizes, int n_in,
                              void* d_out, int out_size)
{
    // Input order: edge_list, edge_weight, edge_feature, [num_node], x,
    //              W_edge, b_edge, W1, b1, W2, b2
    int off = (n_in >= 4 && in_sizes[3] == 1) ? 1 : 0;

    const void*  edge_list = d_in[0];
    const float* ew = (const float*)d_in[1];
    const float* ef = (const float*)d_in[2];
    const float* x  = (const float*)d_in[3 + off];
    const float* We = (const float*)d_in[4 + off];
    const float* be = (const float*)d_in[5 + off];
    const float* W1 = (const float*)d_in[6 + off];
    const float* b1 = (const float*)d_in[7 + off];
    const float* W2 = (const float*)d_in[8 + off];
    const float* b2 = (const float*)d_in[9 + off];
    float* out = (float*)d_out;

    // Prefer the 128-row tile (128 KB smem); fall back to 64-row (96 KB).
    const size_t smem_big   = (16384 + 128 * 32) * sizeof(float4) / 4; // 64KB+64KB
    const size_t smem_small = (16384 + 64 * 32 * 4) * sizeof(float);   // 64KB+32KB
    bool big_ok =
        (cudaFuncSetAttribute(mlp_kernel_t<128>,
                              cudaFuncAttributeMaxDynamicSharedMemorySize,
                              (int)(2 * 16384 * sizeof(float))) == cudaSuccess);
    if (!big_ok)
        (void)cudaFuncSetAttribute(mlp_kernel_t<64>,
                                   cudaFuncAttributeMaxDynamicSharedMemorySize,
                                   (int)smem_small);
    (void)smem_big;

    detect_kernel<<<1, 1>>>((const int*)edge_list);

    {
        int n = N_NODE * D_IN / 4; // covers the eagg range too
        init_kernel<<<(n + 255) / 256, 256>>>(x);
    }

    {
        int warps_per_block = 256 / 32;
        int blocks = (N_EDGE + warps_per_block - 1) / warps_per_block;
        scatter_kernel<<<blocks, 256>>>(edge_list, ew, ef, x);
    }

    {
        int nodes_per_block = 256 / 32;
        int blocks = (N_NODE + nodes_per_block - 1) / nodes_per_block;
        h0_kernel<<<blocks, 256>>>(We, be);
    }

    if (big_ok) {
        int blocks = (N_NODE + 127) / 128; // 782
        size_t sm = 2 * 16384 * sizeof(float);
        mlp_kernel_t<128><<<blocks, 256, sm>>>(W1, b1, nullptr, 0);
        mlp_kernel_t<128><<<blocks, 256, sm>>>(W2, b2, out, 1);
    } else {
        int blocks = (N_NODE + 63) / 64; // 1563
        mlp_kernel_t<64><<<blocks, 256, smem_small>>>(W1, b1, nullptr, 0);
        mlp_kernel_t<64><<<blocks, 256, smem_small>>>(W2, b2, out, 1);
    }
}

// round 5
// speedup vs baseline: 1.2581x; 1.2581x over previous
#include <cuda_runtime.h>

#define N_NODE 100000
#define N_EDGE 1600000
#define D_IN   128
#define D_EDGE 16

// ---------------------------------------------------------------------------
// Scratch (allocation-free: __device__ globals)
__device__ float g_h0  [N_NODE * D_IN];    // fused aggregate + edge-MLP input
__device__ float g_h1  [N_NODE * D_IN];    // only used by fallback MLP path
__device__ int   g_deg    [N_NODE];
__device__ int   g_rowbeg [N_NODE];
__device__ int   g_cursor [N_NODE];
__device__ int   g_srcs   [N_EDGE];
__device__ float g_ws     [N_EDGE];
__device__ int   g_eids   [N_EDGE];
__device__ int   g_is64;

// ---------------------------------------------------------------------------
// Detect whether edge_list is int64 or int32 (int64 < 2^31 -> odd words 0).
__global__ void detect_kernel(const int* el)
{
    int is64 = 1;
    for (int i = 1; i < 4096; i += 2)
        if (el[i] != 0) { is64 = 0; break; }
    g_is64 = is64;
}

// ---------------------------------------------------------------------------
__global__ void zero_deg_kernel()
{
    int i = blockIdx.x * blockDim.x + threadIdx.x;
    if (i < N_NODE) g_deg[i] = 0;
}

// ---------------------------------------------------------------------------
// Degree histogram over dst.
__global__ __launch_bounds__(256) void count_kernel(const void* __restrict__ el_raw)
{
    int e = blockIdx.x * blockDim.x + threadIdx.x;
    if (e >= N_EDGE) return;
    int dst;
    if (g_is64) dst = (int)__ldg(&((const long long*)el_raw)[2 * e + 1]);
    else        dst = __ldg(&((const int*)el_raw)[2 * e + 1]);
    atomicAdd(&g_deg[dst], 1);
}

// ---------------------------------------------------------------------------
// Single-block exclusive scan of g_deg -> g_rowbeg (+ cursor copy).
// 1024 threads, each owns a contiguous chunk of CHUNK elements.
#define SCAN_T 1024
#define CHUNK  ((N_NODE + SCAN_T - 1) / SCAN_T)   // 98
__global__ __launch_bounds__(SCAN_T) void scan_kernel()
{
    __shared__ int part[SCAN_T];
    int t = threadIdx.x;
    int lo = t * CHUNK;
    int hi = min(lo + CHUNK, N_NODE);

    int s = 0;
    for (int i = lo; i < hi; i++) s += g_deg[i];
    part[t] = s;
    __syncthreads();

    // Hillis-Steele inclusive scan of partials
    for (int off = 1; off < SCAN_T; off <<= 1) {
        int v = (t >= off) ? part[t - off] : 0;
        __syncthreads();
        part[t] += v;
        __syncthreads();
    }

    int base = (t == 0) ? 0 : part[t - 1];   // exclusive prefix for this chunk
    for (int i = lo; i < hi; i++) {
        g_rowbeg[i] = base;
        g_cursor[i] = base;
        base += g_deg[i];
    }
}

// ---------------------------------------------------------------------------
// Bucket fill: place (src, w, eid) of each edge into its dst's segment.
__global__ __launch_bounds__(256) void fill_kernel(
    const void* __restrict__ el_raw,
    const float* __restrict__ ew)
{
    int e = blockIdx.x * blockDim.x + threadIdx.x;
    if (e >= N_EDGE) return;
    int src, dst;
    if (g_is64) {
        const long long* el = (const long long*)el_raw;
        src = (int)__ldg(&el[2 * e]);
        dst = (int)__ldg(&el[2 * e + 1]);
    } else {
        const int* el = (const int*)el_raw;
        src = __ldg(&el[2 * e]);
        dst = __ldg(&el[2 * e + 1]);
    }
    int pos = atomicAdd(&g_cursor[dst], 1);
    g_srcs[pos] = src;
    g_ws[pos]   = __ldg(&ew[e]);
    g_eids[pos] = e;
}

// ---------------------------------------------------------------------------
// Fused aggregate + h0. One warp per node:
//   acc  = sum_e w_e * x[src_e]          (float4 per lane, registers)
//   eacc = sum_e w_e * ef[e]             (lanes 0..15, registers)
//   h0   = x[node] + acc + eacc @ W_edge + b_edge   (written once)
__global__ __launch_bounds__(256) void agg_kernel(
    const float* __restrict__ ef,
    const float* __restrict__ x,
    const float* __restrict__ W_edge,
    const float* __restrict__ b_edge)
{
    __shared__ float we[D_EDGE * D_IN];  // 8 KB
    __shared__ float bes[D_IN];
    int tid = threadIdx.x;
    for (int i = tid; i < D_EDGE * D_IN; i += 256) we[i] = W_edge[i];
    if (tid < D_IN) bes[tid] = b_edge[tid];
    __syncthreads();

    int node = (blockIdx.x * 256 + tid) >> 5;
    int lane = tid & 31;
    if (node >= N_NODE) return;

    int beg = g_rowbeg[node];
    int end = beg + g_deg[node];

    float4 acc = make_float4(0.f, 0.f, 0.f, 0.f);
    float  ea  = 0.f;

    for (int e0 = beg; e0 < end; e0 += 32) {
        int n = min(32, end - e0);
        int   s  = 0;
        float wt = 0.f;
        int   id = 0;
        if (lane < n) {
            s  = g_srcs[e0 + lane];
            wt = g_ws  [e0 + lane];
            id = g_eids[e0 + lane];
        }
#pragma unroll 4
        for (int i = 0; i < n; i++) {
            int   si = __shfl_sync(0xffffffffu, s,  i);
            float wi = __shfl_sync(0xffffffffu, wt, i);
            int   ei = __shfl_sync(0xffffffffu, id, i);
            float4 v = __ldg(&((const float4*)x)[(size_t)si * 32 + lane]);
            acc.x += v.x * wi; acc.y += v.y * wi;
            acc.z += v.z * wi; acc.w += v.w * wi;
            if (lane < D_EDGE)
                ea += __ldg(&ef[(size_t)ei * D_EDGE + lane]) * wi;
        }
    }

    // h0 = x + acc + eacc @ W_edge + b_edge
    float4 xr = ((const float4*)x)[(size_t)node * 32 + lane];
    float4 bb = ((const float4*)bes)[lane];
    acc.x += xr.x + bb.x; acc.y += xr.y + bb.y;
    acc.z += xr.z + bb.z; acc.w += xr.w + bb.w;

#pragma unroll
    for (int i = 0; i < D_EDGE; i++) {
        float e = __shfl_sync(0xffffffffu, ea, i);
        float4 wv = ((const float4*)we)[i * 32 + lane];
        acc.x += e * wv.x; acc.y += e * wv.y;
        acc.z += e * wv.z; acc.w += e * wv.w;
    }
    ((float4*)g_h0)[(size_t)node * 32 + lane] = acc;
}

// ---------------------------------------------------------------------------
// Fused 2-layer MLP: out = relu(relu(h0 @ W1 + b1) @ W2 + b2)
// 192 KB dynamic smem: W1 (64K) + W2 (64K) + 128-row tile (64K).
__global__ __launch_bounds__(256, 1) void mlp_fused_kernel(
    const float* __restrict__ W1, const float* __restrict__ b1,
    const float* __restrict__ W2, const float* __restrict__ b2,
    float* __restrict__ out)
{
    extern __shared__ float smem[];
    float* Ws1 = smem;             // 16384 floats
    float* Ws2 = smem + 16384;     // 16384 floats
    float* Is  = smem + 32768;     // 16384 floats (tile, reused for h1)
    __shared__ float bs1[D_IN], bs2[D_IN];

    int tid = threadIdx.x;
    for (int i = tid; i < 4096; i += 256) {
        ((float4*)Ws1)[i] = ((const float4*)W1)[i];
        ((float4*)Ws2)[i] = ((const float4*)W2)[i];
    }
    if (tid < D_IN) { bs1[tid] = b1[tid]; bs2[tid] = b2[tid]; }

    int row0 = blockIdx.x * 128;
    for (int i = tid; i < 4096; i += 256) {
        int r = i >> 5, c = i & 31;
        int row = row0 + r;
        ((float4*)Is)[i] = (row < N_NODE)
            ? ((const float4*)g_h0)[(size_t)row * 32 + c]
            : make_float4(0.f, 0.f, 0.f, 0.f);
    }
    __syncthreads();

    int j4 = tid & 31;   // output float4 column
    int rb = tid >> 5;   // 16-row block

    float4 acc[16];

    // ---- layer 1 ----
#pragma unroll
    for (int r = 0; r < 16; r++) acc[r] = make_float4(0.f, 0.f, 0.f, 0.f);
    for (int k = 0; k < 128; k += 4) {
        float4 w0 = ((const float4*)Ws1)[(k + 0) * 32 + j4];
        float4 w1 = ((const float4*)Ws1)[(k + 1) * 32 + j4];
        float4 w2 = ((const float4*)Ws1)[(k + 2) * 32 + j4];
        float4 w3 = ((const float4*)Ws1)[(k + 3) * 32 + j4];
#pragma unroll
        for (int r = 0; r < 16; r++) {
            float4 a = ((const float4*)Is)[(rb * 16 + r) * 32 + (k >> 2)];
            acc[r].x += a.x * w0.x + a.y * w1.x + a.z * w2.x + a.w * w3.x;
            acc[r].y += a.x * w0.y + a.y * w1.y + a.z * w2.y + a.w * w3.y;
            acc[r].z += a.x * w0.z + a.y * w1.z + a.z * w2.z + a.w * w3.z;
            acc[r].w += a.x * w0.w + a.y * w1.w + a.z * w2.w + a.w * w3.w;
        }
    }
    __syncthreads();   // everyone done reading the input tile
    {
        float4 bb = ((const float4*)bs1)[j4];
#pragma unroll
        for (int r = 0; r < 16; r++) {
            float4 v = acc[r];
            v.x = fmaxf(v.x + bb.x, 0.f);
            v.y = fmaxf(v.y + bb.y, 0.f);
            v.z = fmaxf(v.z + bb.z, 0.f);
            v.w = fmaxf(v.w + bb.w, 0.f);
            ((float4*)Is)[(rb * 16 + r) * 32 + j4] = v;   // h1 tile
        }
    }
    __syncthreads();

    // ---- layer 2 ----
#pragma unroll
    for (int r = 0; r < 16; r++) acc[r] = make_float4(0.f, 0.f, 0.f, 0.f);
    for (int k = 0; k < 128; k += 4) {
        float4 w0 = ((const float4*)Ws2)[(k + 0) * 32 + j4];
        float4 w1 = ((const float4*)Ws2)[(k + 1) * 32 + j4];
        float4 w2 = ((const float4*)Ws2)[(k + 2) * 32 + j4];
        float4 w3 = ((const float4*)Ws2)[(k + 3) * 32 + j4];
#pragma unroll
        for (int r = 0; r < 16; r++) {
            float4 a = ((const float4*)Is)[(rb * 16 + r) * 32 + (k >> 2)];
            acc[r].x += a.x * w0.x + a.y * w1.x + a.z * w2.x + a.w * w3.x;
            acc[r].y += a.x * w0.y + a.y * w1.y + a.z * w2.y + a.w * w3.y;
            acc[r].z += a.x * w0.z + a.y * w1.z + a.z * w2.z + a.w * w3.z;
            acc[r].w += a.x * w0.w + a.y * w1.w + a.z * w2.w + a.w * w3.w;
        }
    }
    {
        float4 bb = ((const float4*)bs2)[j4];
#pragma unroll
        for (int r = 0; r < 16; r++) {
            int row = row0 + rb * 16 + r;
            if (row < N_NODE) {
                float4 v = acc[r];
                v.x = fmaxf(v.x + bb.x, 0.f);
                v.y = fmaxf(v.y + bb.y, 0.f);
                v.z = fmaxf(v.z + bb.z, 0.f);
                v.w = fmaxf(v.w + bb.w, 0.f);
                ((float4*)out)[(size_t)row * 32 + j4] = v;
            }
        }
    }
}

// ---------------------------------------------------------------------------
// Fallback single-layer MLP (128 KB smem) — only if 192 KB opt-in fails.
__global__ __launch_bounds__(256, 1) void mlp_kernel(
    const float* __restrict__ W,
    const float* __restrict__ b,
    float* __restrict__ ext_out,
    int layer)
{
    extern __shared__ float smem[];
    float* Ws = smem;
    float* Is = smem + 16384;
    __shared__ float bs[D_IN];

    const float* in  = (layer == 0) ? g_h0 : g_h1;
    float*       out = (layer == 0) ? g_h1 : ext_out;

    int tid = threadIdx.x;
    for (int i = tid; i < 4096; i += 256)
        ((float4*)Ws)[i] = ((const float4*)W)[i];
    if (tid < D_IN) bs[tid] = b[tid];

    int row0 = blockIdx.x * 128;
    for (int i = tid; i < 4096; i += 256) {
        int r = i >> 5, c = i & 31;
        int row = row0 + r;
        ((float4*)Is)[i] = (row < N_NODE)
            ? ((const float4*)in)[(size_t)row * 32 + c]
            : make_float4(0.f, 0.f, 0.f, 0.f);
    }
    __syncthreads();

    int j4 = tid & 31;
    int rb = tid >> 5;

    float4 acc[16];
#pragma unroll
    for (int r = 0; r < 16; r++) acc[r] = make_float4(0.f, 0.f, 0.f, 0.f);

    for (int k = 0; k < 128; k += 4) {
        float4 w0 = ((const float4*)Ws)[(k + 0) * 32 + j4];
        float4 w1 = ((const float4*)Ws)[(k + 1) * 32 + j4];
        float4 w2 = ((const float4*)Ws)[(k + 2) * 32 + j4];
        float4 w3 = ((const float4*)Ws)[(k + 3) * 32 + j4];
#pragma unroll
        for (int r = 0; r < 16; r++) {
            float4 a = ((const float4*)Is)[(rb * 16 + r) * 32 + (k >> 2)];
            acc[r].x += a.x * w0.x + a.y * w1.x + a.z * w2.x + a.w * w3.x;
            acc[r].y += a.x * w0.y + a.y * w1.y + a.z * w2.y + a.w * w3.y;
            acc[r].z += a.x * w0.z + a.y * w1.z + a.z * w2.z + a.w * w3.z;
            acc[r].w += a.x * w0.w + a.y * w1.w + a.z * w2.w + a.w * w3.w;
        }
    }

    float4 bb = ((const float4*)bs)[j4];
#pragma unroll
    for (int r = 0; r < 16; r++) {
        int row = row0 + rb * 16 + r;
        if (row < N_NODE) {
            float4 v = acc[r];
            v.x = fmaxf(v.x + bb.x, 0.f);
            v.y = fmaxf(v.y + bb.y, 0.f);
            v.z = fmaxf(v.z + bb.z, 0.f);
            v.w = fmaxf(v.w + bb.w, 0.f);
            ((float4*)out)[(size_t)row * 32 + j4] = v;
        }
    }
}

// ---------------------------------------------------------------------------
extern "C" void kernel_launch(void* const* d_in, const int* in_sizes, int n_in,
                              void* d_out, int out_size)
{
    // Input order: edge_list, edge_weight, edge_feature, [num_node], x,
    //              W_edge, b_edge, W1, b1, W2, b2
    int off = (n_in >= 4 && in_sizes[3] == 1) ? 1 : 0;

    const void*  edge_list = d_in[0];
    const float* ew = (const float*)d_in[1];
    const float* ef = (const float*)d_in[2];
    const float* x  = (const float*)d_in[3 + off];
    const float* We = (const float*)d_in[4 + off];
    const float* be = (const float*)d_in[5 + off];
    const float* W1 = (const float*)d_in[6 + off];
    const float* b1 = (const float*)d_in[7 + off];
    const float* W2 = (const float*)d_in[8 + off];
    const float* b2 = (const float*)d_in[9 + off];
    float* out = (float*)d_out;

    const size_t smem_fused = 3 * 16384 * sizeof(float); // 192 KB
    const size_t smem_sep   = 2 * 16384 * sizeof(float); // 128 KB
    bool fused_ok =
        (cudaFuncSetAttribute(mlp_fused_kernel,
                              cudaFuncAttributeMaxDynamicSharedMemorySize,
                              (int)smem_fused) == cudaSuccess);
    if (!fused_ok)
        (void)cudaFuncSetAttribute(mlp_kernel,
                                   cudaFuncAttributeMaxDynamicSharedMemorySize,
                                   (int)smem_sep);

    detect_kernel<<<1, 1>>>((const int*)edge_list);

    // ---- CSR build ----
    zero_deg_kernel<<<(N_NODE + 255) / 256, 256>>>();
    count_kernel<<<(N_EDGE + 255) / 256, 256>>>(edge_list);
    scan_kernel<<<1, SCAN_T>>>();
    fill_kernel<<<(N_EDGE + 255) / 256, 256>>>(edge_list, ew);

    // ---- fused aggregate + h0 ----
    agg_kernel<<<(N_NODE * 32 + 255) / 256, 256>>>(ef, x, We, be);

    // ---- MLP ----
    if (fused_ok) {
        int blocks = (N_NODE + 127) / 128; // 782
        mlp_fused_kernel<<<blocks, 256, smem_fused>>>(W1, b1, W2, b2, out);
    } else {
        int blocks = (N_NODE + 127) / 128;
        mlp_kernel<<<blocks, 256, smem_sep>>>(W1, b1, nullptr, 0);
        mlp_kernel<<<blocks, 256, smem_sep>>>(W2, b2, out, 1);
    }
}